// round 3
// baseline (speedup 1.0000x reference)
#include <cuda_runtime.h>

// 7-level db4 DWT -> soft threshold -> IDWT, fully fused in SMEM.
// One CTA per row. R3: 4-wide forward units, 8-wide inverse units (all
// LDS.128/STS.128), final inverse level streams straight to gmem.

#define NTHREADS 128
#define NROWS    32768
#define N0       1116

static __constant__ float DLO[8] = {
    -0.010597401784997278f,  0.032883011666982945f,  0.030841381835986965f,
    -0.18703481171888114f,  -0.02798376941698385f,   0.6308807679295904f,
     0.7148465705525415f,    0.23037781330885523f
};
static __constant__ float DHI[8] = {
    -0.23037781330885523f,   0.7148465705525415f,   -0.6308807679295904f,
    -0.02798376941698385f,   0.18703481171888114f,   0.030841381835986965f,
    -0.032883011666982945f, -0.010597401784997278f
};

__device__ __forceinline__ float softf(float c, float t) {
    return copysignf(fmaxf(fabsf(c) - t, 0.0f), c);
}

// ---- forward level, 4 outputs per unit. Input physical (pad-6 layout),
// approx written at phys 6+j with zero-fill halo, details at 16B-aligned dph.
template<int M, bool LAST, int NTH>
__device__ __forceinline__ void fwd4(const float* __restrict__ a,
                                     float* __restrict__ an,
                                     float* __restrict__ dph,
                                     float thr, int tid)
{
    constexpr int UNITS = (M + 3) / 4 + 4;   // extra units zero-fill next level's halo
    for (int t = tid; t < UNITS; t += NTH) {
        float r[16];
        *(float4*)(r)      = *(const float4*)(a + 8 * t);
        *(float4*)(r + 4)  = *(const float4*)(a + 8 * t + 4);
        *(float4*)(r + 8)  = *(const float4*)(a + 8 * t + 8);
        *(float4*)(r + 12) = *(const float4*)(a + 8 * t + 12);
        float ca[4], cd[4];
        #pragma unroll
        for (int i = 0; i < 4; i++) {
            float e = 0.f, f = 0.f;
            #pragma unroll
            for (int k = 0; k < 8; k++) {
                e = fmaf(r[2 * i + k], DLO[7 - k], e);
                f = fmaf(r[2 * i + k], DHI[7 - k], f);
            }
            if (LAST) e = softf(e, thr);
            ca[i] = e;
            cd[i] = softf(f, thr);
        }
        const int j0 = 4 * t;
        *(float2*)(an + 6 + j0) = make_float2(j0     < M ? ca[0] : 0.f,
                                              j0 + 1 < M ? ca[1] : 0.f);
        *(float2*)(an + 8 + j0) = make_float2(j0 + 2 < M ? ca[2] : 0.f,
                                              j0 + 3 < M ? ca[3] : 0.f);
        if (j0 + 3 < M) {
            *(float4*)(dph + j0) = make_float4(cd[0], cd[1], cd[2], cd[3]);
        } else if (j0 < M) {
            #pragma unroll
            for (int i = 0; i < 3; i++)
                if (j0 + i < M) dph[j0 + i] = cd[i];
        }
    }
}

// ---- forward level, 2 outputs per unit (tiny levels, one warp)
template<int M, bool LAST, int NTH>
__device__ __forceinline__ void fwd2(const float* __restrict__ a,
                                     float* __restrict__ an,
                                     float* __restrict__ dph,
                                     float thr, int tid)
{
    constexpr int PAD = (M + 1) / 2 + 8;
    for (int t = tid; t < PAD; t += NTH) {
        const float4 v0 = *(const float4*)(a + 4 * t);
        const float4 v1 = *(const float4*)(a + 4 * t + 4);
        const float4 v2 = *(const float4*)(a + 4 * t + 8);
        const float r[12] = {v0.x, v0.y, v0.z, v0.w, v1.x, v1.y, v1.z, v1.w,
                             v2.x, v2.y, v2.z, v2.w};
        float ca0 = 0.f, cd0 = 0.f, ca1 = 0.f, cd1 = 0.f;
        #pragma unroll
        for (int k = 0; k < 8; k++) {
            ca0 = fmaf(r[k],     DLO[7 - k], ca0);
            cd0 = fmaf(r[k],     DHI[7 - k], cd0);
            ca1 = fmaf(r[k + 2], DLO[7 - k], ca1);
            cd1 = fmaf(r[k + 2], DHI[7 - k], cd1);
        }
        cd0 = softf(cd0, thr); cd1 = softf(cd1, thr);
        if (LAST) { ca0 = softf(ca0, thr); ca1 = softf(ca1, thr); }
        const int j0 = 2 * t;
        *(float2*)(an + 6 + j0) = make_float2(j0 < M ? ca0 : 0.f,
                                              (j0 + 1) < M ? ca1 : 0.f);
        if (j0 < M)
            *(float2*)(dph + j0) = make_float2(cd0, (j0 + 1) < M ? cd1 : 0.f);
    }
}

// ---- inverse level, 4 outputs per unit (tiny levels)
template<int MD, int NTH>
__device__ __forceinline__ void inv4(const float* __restrict__ a,
                                     const float* __restrict__ d,
                                     float* __restrict__ o, int tid)
{
    constexpr int OLEN  = 2 * MD - 6;
    constexpr int QUADS = (OLEN + 3) / 4;
    for (int u = tid; u < QUADS; u += NTH) {
        const int s = 2 * u;
        const float2 a01 = *(const float2*)(a + s);
        const float2 a23 = *(const float2*)(a + s + 2);
        const float  a4  = a[s + 4];
        const float2 d01 = *(const float2*)(d + s);
        const float2 d23 = *(const float2*)(d + s + 2);
        const float  d4  = d[s + 4];
        float o0 = a01.x * DLO[1];  o0 = fmaf(a01.y, DLO[3], o0);
        o0 = fmaf(a23.x, DLO[5], o0); o0 = fmaf(a23.y, DLO[7], o0);
        o0 = fmaf(d01.x, DHI[1], o0); o0 = fmaf(d01.y, DHI[3], o0);
        o0 = fmaf(d23.x, DHI[5], o0); o0 = fmaf(d23.y, DHI[7], o0);
        float o1 = a01.x * DLO[0];  o1 = fmaf(a01.y, DLO[2], o1);
        o1 = fmaf(a23.x, DLO[4], o1); o1 = fmaf(a23.y, DLO[6], o1);
        o1 = fmaf(d01.x, DHI[0], o1); o1 = fmaf(d01.y, DHI[2], o1);
        o1 = fmaf(d23.x, DHI[4], o1); o1 = fmaf(d23.y, DHI[6], o1);
        float o2 = a01.y * DLO[1];  o2 = fmaf(a23.x, DLO[3], o2);
        o2 = fmaf(a23.y, DLO[5], o2); o2 = fmaf(a4,   DLO[7], o2);
        o2 = fmaf(d01.y, DHI[1], o2); o2 = fmaf(d23.x, DHI[3], o2);
        o2 = fmaf(d23.y, DHI[5], o2); o2 = fmaf(d4,   DHI[7], o2);
        float o3 = a01.y * DLO[0];  o3 = fmaf(a23.x, DLO[2], o3);
        o3 = fmaf(a23.y, DLO[4], o3); o3 = fmaf(a4,   DLO[6], o3);
        o3 = fmaf(d01.y, DHI[0], o3); o3 = fmaf(d23.x, DHI[2], o3);
        o3 = fmaf(d23.y, DHI[4], o3); o3 = fmaf(d4,   DHI[6], o3);
        if (4 * u + 3 < OLEN) *(float4*)(o + 4 * u) = make_float4(o0, o1, o2, o3);
        else                  *(float2*)(o + 4 * u) = make_float2(o0, o1);
    }
}

// ---- inverse level, 8 outputs per unit (big levels); o may be gmem.
template<int MD, int NTH>
__device__ __forceinline__ void inv8(const float* __restrict__ a,
                                     const float* __restrict__ d,
                                     float* __restrict__ o, int tid)
{
    constexpr int OLEN  = 2 * MD - 6;
    constexpr int UNITS = (OLEN + 7) / 8;
    for (int w = tid; w < UNITS; w += NTH) {
        float A[8], D[8];
        *(float4*)(A)     = *(const float4*)(a + 4 * w);
        *(float4*)(A + 4) = *(const float4*)(a + 4 * w + 4);
        *(float4*)(D)     = *(const float4*)(d + 4 * w);
        *(float4*)(D + 4) = *(const float4*)(d + 4 * w + 4);
        float o8[8];
        #pragma unroll
        for (int p = 0; p < 4; p++) {
            float e = 0.f, f = 0.f;
            #pragma unroll
            for (int j = 0; j < 4; j++) {
                e = fmaf(A[p + j], DLO[2 * j + 1], e);
                e = fmaf(D[p + j], DHI[2 * j + 1], e);
                f = fmaf(A[p + j], DLO[2 * j],     f);
                f = fmaf(D[p + j], DHI[2 * j],     f);
            }
            o8[2 * p] = e; o8[2 * p + 1] = f;
        }
        const int t0 = 8 * w;
        if (t0 + 7 < OLEN) {
            *(float4*)(o + t0)     = make_float4(o8[0], o8[1], o8[2], o8[3]);
            *(float4*)(o + t0 + 4) = make_float4(o8[4], o8[5], o8[6], o8[7]);
        } else {
            const int rem = OLEN - t0;   // 2, 4 or 6
            if (rem >= 4) {
                *(float4*)(o + t0) = make_float4(o8[0], o8[1], o8[2], o8[3]);
                if (rem == 6) *(float2*)(o + t0 + 4) = make_float2(o8[4], o8[5]);
            } else {
                *(float2*)(o + t0) = make_float2(o8[0], o8[1]);
            }
        }
    }
}

__global__ __launch_bounds__(NTHREADS)
void wavelet_fused_kernel(const float* __restrict__ x,
                          const float* __restrict__ rawthr,
                          float* __restrict__ out)
{
    // Level lengths: {1116, 561, 284, 145, 76, 41, 24, 15}
    __shared__ __align__(16) float sA[1168];
    __shared__ __align__(16) float sB[640];
    __shared__ __align__(16) float sD[1160]; // doff: 0,564,848,996,1072,1116,1140

    const int row = blockIdx.x;
    const int tid = threadIdx.x;
    const float thr = fmaxf(rawthr[0], 0.01f);

    // ---- zero halos + load row (logical x[i] at sA[6+i])
    {
        const float4 z4 = make_float4(0.f, 0.f, 0.f, 0.f);
        #pragma unroll
        for (int i = tid; i < 640 / 4; i += NTHREADS) ((float4*)sB)[i] = z4;
        if (tid < 6) sA[tid] = 0.f;
        for (int i = 1122 + tid; i < 1168; i += NTHREADS) sA[i] = 0.f;

        const float4* __restrict__ xin = (const float4*)(x + (size_t)row * N0);
        #pragma unroll
        for (int q = tid; q < N0 / 4; q += NTHREADS) {
            const float4 v = xin[q];
            *(float2*)(sA + 6 + 4 * q) = make_float2(v.x, v.y);
            *(float2*)(sA + 8 + 4 * q) = make_float2(v.z, v.w);
        }
    }
    __syncthreads();

    // ---- forward DWT, big levels
    fwd4<561, false, NTHREADS>(sA, sB, sD + 0,   thr, tid); __syncthreads();
    fwd4<284, false, NTHREADS>(sB, sA, sD + 564, thr, tid); __syncthreads();
    fwd4<145, false, NTHREADS>(sA, sB, sD + 848, thr, tid); __syncthreads();
    fwd4<76,  false, NTHREADS>(sB, sA, sD + 996, thr, tid); __syncthreads();

    // ---- tiny levels: single warp
    if (tid < 32) {
        fwd2<41, false, 32>(sA, sB, sD + 1072, thr, tid); __syncwarp();
        fwd2<24, false, 32>(sB, sA, sD + 1116, thr, tid); __syncwarp();
        fwd2<15, true,  32>(sA, sB, sD + 1140, thr, tid); __syncwarp();
        inv4<15, 32>(sB + 6, sD + 1140, sA + 8, tid);     __syncwarp();
        inv4<24, 32>(sA + 8, sD + 1116, sB + 8, tid);     __syncwarp();
        inv4<41, 32>(sB + 8, sD + 1072, sA + 8, tid);
    }
    __syncthreads();

    // ---- inverse DWT, big levels (last streams straight to gmem)
    inv8<76,  NTHREADS>(sA + 8, sD + 996, sB + 8, tid); __syncthreads();
    inv8<145, NTHREADS>(sB + 8, sD + 848, sA + 8, tid); __syncthreads();
    inv8<284, NTHREADS>(sA + 8, sD + 564, sB + 8, tid); __syncthreads();
    inv8<561, NTHREADS>(sB + 8, sD + 0, out + (size_t)row * N0, tid);
}

extern "C" void kernel_launch(void* const* d_in, const int* in_sizes, int n_in,
                              void* d_out, int out_size)
{
    const float* x    = (const float*)d_in[0];
    const float* rthr = (const float*)d_in[1];
    float* out        = (float*)d_out;
    wavelet_fused_kernel<<<NROWS, NTHREADS>>>(x, rthr, out);
}

// round 4
// speedup vs baseline: 1.1344x; 1.1344x over previous
#include <cuda_runtime.h>

// 7-level db4 DWT -> soft threshold -> IDWT, fully fused in SMEM.
// One CTA per row; dense (16B-thread-stride) vector LDS/STS throughout.
// R4: level-1 forward reads gmem directly; final inverse streams to gmem.

#define NTHREADS 128
#define NROWS    32768
#define N0       1116

static __constant__ float DLO[8] = {
    -0.010597401784997278f,  0.032883011666982945f,  0.030841381835986965f,
    -0.18703481171888114f,  -0.02798376941698385f,   0.6308807679295904f,
     0.7148465705525415f,    0.23037781330885523f
};
static __constant__ float DHI[8] = {
    -0.23037781330885523f,   0.7148465705525415f,   -0.6308807679295904f,
    -0.02798376941698385f,   0.18703481171888114f,   0.030841381835986965f,
    -0.032883011666982945f, -0.010597401784997278f
};

__device__ __forceinline__ float softf(float c, float t) {
    return copysignf(fmaxf(fabsf(c) - t, 0.0f), c);
}

// ---- forward level 1: read row directly from gmem (x logical, zero-extended).
// Writes approx (with zero halo) at an phys 6+j, details (thresholded) at dph.
template<int NTH>
__device__ __forceinline__ void fwd_gmem(const float* __restrict__ x,
                                         float* __restrict__ an,
                                         float* __restrict__ dph,
                                         float thr, int tid)
{
    constexpr int M   = 561;
    constexpr int PAD = (M + 1) / 2 + 8;   // 289: extras zero-fill next level halo
    for (int t = tid; t < PAD; t += NTH) {
        // need logical x[4t-6 .. 4t+6); load aligned blocks [4t-8, 4t+8)
        float r[16];
        const int b0 = 4 * t - 8;
        #pragma unroll
        for (int bi = 0; bi < 4; bi++) {
            const int idx = b0 + 4 * bi;
            float4 v = make_float4(0.f, 0.f, 0.f, 0.f);
            if (idx >= 0 && idx + 4 <= N0) v = *(const float4*)(x + idx);
            *(float4*)(r + 4 * bi) = v;
        }
        float ca0 = 0.f, cd0 = 0.f, ca1 = 0.f, cd1 = 0.f;
        #pragma unroll
        for (int k = 0; k < 8; k++) {
            ca0 = fmaf(r[2 + k], DLO[7 - k], ca0);   // j = 2t
            cd0 = fmaf(r[2 + k], DHI[7 - k], cd0);
            ca1 = fmaf(r[4 + k], DLO[7 - k], ca1);   // j = 2t+1
            cd1 = fmaf(r[4 + k], DHI[7 - k], cd1);
        }
        cd0 = softf(cd0, thr); cd1 = softf(cd1, thr);
        const int j0 = 2 * t;
        *(float2*)(an + 6 + j0) = make_float2(j0 < M ? ca0 : 0.f,
                                              (j0 + 1) < M ? ca1 : 0.f);
        if (j0 < M)
            *(float2*)(dph + j0) = make_float2(cd0, (j0 + 1) < M ? cd1 : 0.f);
    }
}

// ---- forward SMEM level, 2 outputs/unit, dense 16B-stride LDS.128.
template<int M, bool LAST, int NTH>
__device__ __forceinline__ void fwd_level(const float* __restrict__ a,
                                          float* __restrict__ an,
                                          float* __restrict__ dph,
                                          float thr, int tid)
{
    constexpr int PAD = (M + 1) / 2 + 8;
    for (int t = tid; t < PAD; t += NTH) {
        const float4 v0 = *(const float4*)(a + 4 * t);
        const float4 v1 = *(const float4*)(a + 4 * t + 4);
        const float4 v2 = *(const float4*)(a + 4 * t + 8);
        const float r[12] = {v0.x, v0.y, v0.z, v0.w, v1.x, v1.y, v1.z, v1.w,
                             v2.x, v2.y, v2.z, v2.w};
        float ca0 = 0.f, cd0 = 0.f, ca1 = 0.f, cd1 = 0.f;
        #pragma unroll
        for (int k = 0; k < 8; k++) {
            ca0 = fmaf(r[k],     DLO[7 - k], ca0);
            cd0 = fmaf(r[k],     DHI[7 - k], cd0);
            ca1 = fmaf(r[k + 2], DLO[7 - k], ca1);
            cd1 = fmaf(r[k + 2], DHI[7 - k], cd1);
        }
        cd0 = softf(cd0, thr); cd1 = softf(cd1, thr);
        if (LAST) { ca0 = softf(ca0, thr); ca1 = softf(ca1, thr); }
        const int j0 = 2 * t;
        *(float2*)(an + 6 + j0) = make_float2(j0 < M ? ca0 : 0.f,
                                              (j0 + 1) < M ? ca1 : 0.f);
        if (j0 < M)
            *(float2*)(dph + j0) = make_float2(cd0, (j0 + 1) < M ? cd1 : 0.f);
    }
}

// ---- inverse level, 4 outputs/unit, dense 8B-stride loads, 16B stores.
// Vector overshoot reads only feed unstored lanes (stays inside the arrays).
template<int MD, int NTH>
__device__ __forceinline__ void inv_level(const float* __restrict__ a,
                                          const float* __restrict__ d,
                                          float* __restrict__ o, int tid)
{
    constexpr int OLEN  = 2 * MD - 6;
    constexpr int QUADS = (OLEN + 3) / 4;
    for (int u = tid; u < QUADS; u += NTH) {
        const int s = 2 * u;
        const float2 a01 = *(const float2*)(a + s);
        const float2 a23 = *(const float2*)(a + s + 2);
        const float  a4  = a[s + 4];
        const float2 d01 = *(const float2*)(d + s);
        const float2 d23 = *(const float2*)(d + s + 2);
        const float  d4  = d[s + 4];
        float o0 = a01.x * DLO[1];  o0 = fmaf(a01.y, DLO[3], o0);
        o0 = fmaf(a23.x, DLO[5], o0); o0 = fmaf(a23.y, DLO[7], o0);
        o0 = fmaf(d01.x, DHI[1], o0); o0 = fmaf(d01.y, DHI[3], o0);
        o0 = fmaf(d23.x, DHI[5], o0); o0 = fmaf(d23.y, DHI[7], o0);
        float o1 = a01.x * DLO[0];  o1 = fmaf(a01.y, DLO[2], o1);
        o1 = fmaf(a23.x, DLO[4], o1); o1 = fmaf(a23.y, DLO[6], o1);
        o1 = fmaf(d01.x, DHI[0], o1); o1 = fmaf(d01.y, DHI[2], o1);
        o1 = fmaf(d23.x, DHI[4], o1); o1 = fmaf(d23.y, DHI[6], o1);
        float o2 = a01.y * DLO[1];  o2 = fmaf(a23.x, DLO[3], o2);
        o2 = fmaf(a23.y, DLO[5], o2); o2 = fmaf(a4,   DLO[7], o2);
        o2 = fmaf(d01.y, DHI[1], o2); o2 = fmaf(d23.x, DHI[3], o2);
        o2 = fmaf(d23.y, DHI[5], o2); o2 = fmaf(d4,   DHI[7], o2);
        float o3 = a01.y * DLO[0];  o3 = fmaf(a23.x, DLO[2], o3);
        o3 = fmaf(a23.y, DLO[4], o3); o3 = fmaf(a4,   DLO[6], o3);
        o3 = fmaf(d01.y, DHI[0], o3); o3 = fmaf(d23.x, DHI[2], o3);
        o3 = fmaf(d23.y, DHI[4], o3); o3 = fmaf(d4,   DHI[6], o3);
        if (4 * u + 3 < OLEN) *(float4*)(o + 4 * u) = make_float4(o0, o1, o2, o3);
        else                  *(float2*)(o + 4 * u) = make_float2(o0, o1);
    }
}

__global__ __launch_bounds__(NTHREADS)
void wavelet_fused_kernel(const float* __restrict__ x,
                          const float* __restrict__ rawthr,
                          float* __restrict__ out)
{
    // Level lengths: {1116, 561, 284, 145, 76, 41, 24, 15}
    __shared__ __align__(16) float sA[1168];
    __shared__ __align__(16) float sB[640];
    __shared__ __align__(16) float sD[1152];  // doff: 0,562,846,992,1068,1110,1134

    const int row = blockIdx.x;
    const int tid = threadIdx.x;
    const float thr = fmaxf(__ldg(rawthr), 0.01f);
    const float* __restrict__ xr = x + (size_t)row * N0;

    // ---- residual zero-fill (regions never overwritten before their reads):
    //   sA[0:6)  — read by fwd<145>, fwd<41>, fwd<15>
    //   sB[0:6)  — read by fwd<284>, fwd<76>, fwd<24>
    //   sB[584:640) — read by fwd<284> tail window
    if (tid < 6)       { sA[tid] = 0.f; sB[tid] = 0.f; }
    if (tid >= 64 && tid < 64 + 56) sB[520 + tid] = 0.f;   // 584..639
    __syncthreads();

    // ---- forward DWT (level 1 straight from gmem)
    fwd_gmem<NTHREADS>(xr, sB, sD + 0, thr, tid);                 __syncthreads();
    fwd_level<284, false, NTHREADS>(sB, sA, sD + 562, thr, tid);  __syncthreads();
    fwd_level<145, false, NTHREADS>(sA, sB, sD + 846, thr, tid);  __syncthreads();
    fwd_level<76,  false, NTHREADS>(sB, sA, sD + 992, thr, tid);  __syncthreads();

    // ---- tiny levels: single warp, __syncwarp only
    if (tid < 32) {
        fwd_level<41, false, 32>(sA, sB, sD + 1068, thr, tid); __syncwarp();
        fwd_level<24, false, 32>(sB, sA, sD + 1110, thr, tid); __syncwarp();
        fwd_level<15, true,  32>(sA, sB, sD + 1134, thr, tid); __syncwarp();
        inv_level<15, 32>(sB + 6, sD + 1134, sA + 8, tid);     __syncwarp();
        inv_level<24, 32>(sA + 8, sD + 1110, sB + 8, tid);     __syncwarp();
        inv_level<41, 32>(sB + 8, sD + 1068, sA + 8, tid);
    }
    __syncthreads();

    // ---- inverse DWT, big levels; final level streams to gmem (1116 % 4 == 0
    // -> every store is a dense STG.128, no tail)
    inv_level<76,  NTHREADS>(sA + 8, sD + 992, sB + 8, tid); __syncthreads();
    inv_level<145, NTHREADS>(sB + 8, sD + 846, sA + 8, tid); __syncthreads();
    inv_level<284, NTHREADS>(sA + 8, sD + 562, sB + 8, tid); __syncthreads();
    inv_level<561, NTHREADS>(sB + 8, sD + 0, out + (size_t)row * N0, tid);
}

extern "C" void kernel_launch(void* const* d_in, const int* in_sizes, int n_in,
                              void* d_out, int out_size)
{
    const float* x    = (const float*)d_in[0];
    const float* rthr = (const float*)d_in[1];
    float* out        = (float*)d_out;
    wavelet_fused_kernel<<<NROWS, NTHREADS>>>(x, rthr, out);
}